// round 11
// baseline (speedup 1.0000x reference)
#include <cuda_runtime.h>

#define D 64
#define MAX_NODES 150016
#define MAX_EDGES_PAD (2000000 + 4 * MAX_NODES)   // padded-to-4 CSR capacity
#define SCAN_B 512
#define MAX_BLKS ((MAX_NODES + SCAN_B - 1) / SCAN_B)
#define NBINS 64

// Static scratch (allocation-free rule). Kernels bind these symbols directly;
// never passed from host as kernel args (host-side decay bug, R4).
__device__ float g_x[(size_t)MAX_NODES * D];    // x0 concat, later x2
__device__ float g_y[(size_t)MAX_NODES * D];    // x1
__device__ float g_b3[(size_t)MAX_NODES * D];   // x3 (sampled rows only)
__device__ int   g_cnt[MAX_NODES];              // per-dst edge counts
__device__ int   g_off[MAX_NODES + 1];          // padded CSR offsets (4-aligned)
__device__ int   g_cur[MAX_NODES];              // scatter cursors
__device__ int   g_bsum[MAX_BLKS];              // per-block sums for scan
__device__ int   g_dcnt[NBINS];                 // degree-bin histogram
__device__ int   g_dcur[NBINS];                 // degree-bin cursors
__device__ int   g_perm[MAX_NODES];             // degree-sorted node order
__device__ int2  g_edge[MAX_EDGES_PAD];         // dst-grouped (src, w-bits), padded

// Concatenate embeddings into g_x (x0); zero histogram counters.
__global__ void init_kernel(const float* __restrict__ ue,
                            const float* __restrict__ ie,
                            int n_user_f, int n4, int n_nodes) {
    int i = blockIdx.x * blockDim.x + threadIdx.x;   // float4 index
    if (i < n_nodes) g_cnt[i] = 0;
    if (i < NBINS)   g_dcnt[i] = 0;
    if (i >= n4) return;
    int f = i << 2;
    float4 v = (f < n_user_f) ? ((const float4*)ue)[i]
                              : ((const float4*)ie)[i - (n_user_f >> 2)];
    ((float4*)g_x)[i] = v;
}

__global__ void hist_kernel(const int* __restrict__ dst, int n_edges) {
    int e = blockIdx.x * blockDim.x + threadIdx.x;
    if (e < n_edges) atomicAdd(&g_cnt[dst[e]], 1);
}

// Block-wide inclusive scan of one int per thread (SCAN_B threads).
__device__ __forceinline__ int block_incl_scan(int v) {
    __shared__ int wsum[SCAN_B / 32];
    int lane = threadIdx.x & 31;
    int wid  = threadIdx.x >> 5;
    int x = v;
    #pragma unroll
    for (int o = 1; o < 32; o <<= 1) {
        int t = __shfl_up_sync(0xffffffffu, x, o);
        if (lane >= o) x += t;
    }
    if (lane == 31) wsum[wid] = x;
    __syncthreads();
    if (wid == 0) {
        int w = (lane < SCAN_B / 32) ? wsum[lane] : 0;
        #pragma unroll
        for (int o = 1; o < SCAN_B / 32; o <<= 1) {
            int t = __shfl_up_sync(0xffffffffu, w, o);
            if (lane >= o) w += t;
        }
        if (lane < SCAN_B / 32) wsum[lane] = w;
    }
    __syncthreads();
    return x + (wid ? wsum[wid - 1] : 0);
}

// Scan of PADDED counts ((cnt+3)&~3) -> 4-aligned row extents.
__global__ void scanA_kernel(int n) {
    int i = blockIdx.x * SCAN_B + threadIdx.x;
    int v = (i < n) ? ((g_cnt[i] + 3) & ~3) : 0;
    int inc = block_incl_scan(v);
    if (i < n) g_off[i] = inc - v;
    if (threadIdx.x == SCAN_B - 1) g_bsum[blockIdx.x] = inc;
}

__global__ void scanB_kernel(int nblk, int n) {
    int v = (threadIdx.x < nblk) ? g_bsum[threadIdx.x] : 0;
    int inc = block_incl_scan(v);
    if (threadIdx.x < nblk) g_bsum[threadIdx.x] = inc - v;
    if (threadIdx.x == SCAN_B - 1) g_off[n] = inc;
}

// Add block offsets; scatter cursor starts at the row start.
__global__ void scanC_kernel(int n) {
    int i = blockIdx.x * SCAN_B + threadIdx.x;
    if (i < n) {
        int o = g_off[i] + g_bsum[blockIdx.x];
        g_off[i] = o;
        g_cur[i] = o;
    }
}

// Zero pad slots (<=3 per node) and build the degree-bin histogram
// (bin = padded iteration count, clamped).
__global__ void nodeprep_kernel(int n) {
    __shared__ int sh[NBINS];
    if (threadIdx.x < NBINS) sh[threadIdx.x] = 0;
    __syncthreads();
    int i = blockIdx.x * blockDim.x + threadIdx.x;
    if (i < n) {
        int cnt = g_cnt[i];
        int beg = g_off[i] + cnt;
        int end = g_off[i] + ((cnt + 3) & ~3);
        for (int j = beg; j < end; j++) g_edge[j] = make_int2(0, 0);
        int bin = (cnt + 3) >> 2;
        if (bin > NBINS - 1) bin = NBINS - 1;
        atomicAdd(&sh[bin], 1);
    }
    __syncthreads();
    if (threadIdx.x < NBINS && sh[threadIdx.x])
        atomicAdd(&g_dcnt[threadIdx.x], sh[threadIdx.x]);
}

// Exclusive scan of the 64 degree bins -> bin cursors.
__global__ void dscan_kernel() {
    __shared__ int sh[NBINS];
    int tid = threadIdx.x;
    int v = g_dcnt[tid];
    sh[tid] = v;
    __syncthreads();
    for (int o = 1; o < NBINS; o <<= 1) {
        int t = (tid >= o) ? sh[tid - o] : 0;
        __syncthreads();
        sh[tid] += t;
        __syncthreads();
    }
    g_dcur[tid] = sh[tid] - v;   // exclusive prefix
}

// Scatter nodes into degree-sorted order.
__global__ void dscatter_kernel(int n) {
    int i = blockIdx.x * blockDim.x + threadIdx.x;
    if (i >= n) return;
    int bin = (g_cnt[i] + 3) >> 2;
    if (bin > NBINS - 1) bin = NBINS - 1;
    int pos = atomicAdd(&g_dcur[bin], 1);
    g_perm[pos] = i;
}

__global__ void scatter_kernel(const int* __restrict__ src,
                               const int* __restrict__ dst,
                               const float* __restrict__ w, int n_edges) {
    int e = blockIdx.x * blockDim.x + threadIdx.x;
    if (e >= n_edges) return;
    int d = dst[e];
    int pos = atomicAdd(&g_cur[d], 1);
    g_edge[pos] = make_int2(src[e], __float_as_int(w[e]));
}

// Row-gather over the padded 4-aligned extent: two int4 edge loads + 4
// independent gathers per iteration; no remainder (pads contribute 0).
__device__ __forceinline__ float4 row_gather(const float* __restrict__ x,
                                             int node, int c) {
    int beg = g_off[node];
    int end = g_off[node + 1];
    float4 a = make_float4(0.f, 0.f, 0.f, 0.f);
    #pragma unroll 2
    for (int i = beg; i < end; i += 4) {
        int4 e01 = *(const int4*)(g_edge + i);       // (s0,w0,s1,w1)
        int4 e23 = *(const int4*)(g_edge + i + 2);   // (s2,w2,s3,w3)
        float4 v0 = *(const float4*)(x + (size_t)e01.x * D + c);
        float4 v1 = *(const float4*)(x + (size_t)e01.z * D + c);
        float4 v2 = *(const float4*)(x + (size_t)e23.x * D + c);
        float4 v3 = *(const float4*)(x + (size_t)e23.z * D + c);
        float w0 = __int_as_float(e01.y);
        float w1 = __int_as_float(e01.w);
        float w2 = __int_as_float(e23.y);
        float w3 = __int_as_float(e23.w);
        a.x += w0 * v0.x + w1 * v1.x + w2 * v2.x + w3 * v3.x;
        a.y += w0 * v0.y + w1 * v1.y + w2 * v2.y + w3 * v3.y;
        a.z += w0 * v0.z + w1 * v1.z + w2 * v2.z + w3 * v3.z;
        a.w += w0 * v0.w + w1 * v1.w + w2 * v2.w + w3 * v3.w;
    }
    return a;
}

// Dense SpMM over degree-sorted nodes. flip=0: g_x -> g_y; flip=1: g_y -> g_x.
__global__ void spmm_dense_kernel(int n_nodes, int flip) {
    const float* __restrict__ x = flip ? g_y : g_x;
    float*                    y = flip ? g_x : g_y;
    int t = blockIdx.x * blockDim.x + threadIdx.x;
    int ni = t >> 4;
    if (ni >= n_nodes) return;
    int node = g_perm[ni];                 // degree-sorted order
    int c = (t & 15) << 2;
    float4 a = row_gather(x, node, c);
    *(float4*)(y + (size_t)node * D + c) = a;   // full overwrite
}

// Sparse-output SpMM (layer 3): g_x (x2) -> g_b3, only sampled rows.
__global__ void spmm_list_kernel(const int* __restrict__ users,
                                 const int* __restrict__ items,
                                 int B, int n_users) {
    int t = blockIdx.x * blockDim.x + threadIdx.x;
    int li = t >> 4;
    if (li >= 2 * B) return;
    int node = (li < B) ? users[li] : n_users + items[li - B];
    int c = (t & 15) << 2;
    float4 a = row_gather(g_x, node, c);
    *(float4*)(g_b3 + (size_t)node * D + c) = a;
}

// One warp per (user, item) pair. Final row = (x0+x1+x2+x3)/4 on the fly
// from ue/ie, g_y(x1), g_x(x2), g_b3(x3). 1/16 folded into the dot.
__global__ void score_kernel(const float* __restrict__ ue,
                             const float* __restrict__ ie,
                             const int* __restrict__ users,
                             const int* __restrict__ items,
                             float* __restrict__ out, int B, int n_users) {
    int g    = blockIdx.x * blockDim.x + threadIdx.x;
    int pair = g >> 5;
    int lane = threadIdx.x & 31;
    if (pair >= B) return;
    int un = users[pair];
    int in = items[pair];
    int ir = n_users + in;
    size_t uo = (size_t)un * D;
    size_t io = (size_t)ir * D;
    float2 u0 = ((const float2*)(ue + uo))[lane];
    float2 u1 = ((const float2*)(g_y + uo))[lane];
    float2 u2 = ((const float2*)(g_x + uo))[lane];
    float2 u3 = ((const float2*)(g_b3 + uo))[lane];
    float2 v0 = ((const float2*)(ie + (size_t)in * D))[lane];
    float2 v1 = ((const float2*)(g_y + io))[lane];
    float2 v2 = ((const float2*)(g_x + io))[lane];
    float2 v3 = ((const float2*)(g_b3 + io))[lane];
    float ux = u0.x + u1.x + u2.x + u3.x;
    float uy = u0.y + u1.y + u2.y + u3.y;
    float vx = v0.x + v1.x + v2.x + v3.x;
    float vy = v0.y + v1.y + v2.y + v3.y;
    float s = ux * vx + uy * vy;
    #pragma unroll
    for (int o = 16; o; o >>= 1) s += __shfl_xor_sync(0xffffffffu, s, o);
    if (lane == 0) out[pair] = s * (1.0f / 16.0f);
}

extern "C" void kernel_launch(void* const* d_in, const int* in_sizes, int n_in,
                              void* d_out, int out_size) {
    const float* ue    = (const float*)d_in[0];
    const float* ie    = (const float*)d_in[1];
    const int*   esrc  = (const int*)  d_in[2];
    const int*   edst  = (const int*)  d_in[3];
    const float* ew    = (const float*)d_in[4];
    const int*   users = (const int*)  d_in[5];
    const int*   items = (const int*)  d_in[6];

    int n_user_f  = in_sizes[0];
    int n_item_f  = in_sizes[1];
    int n_edges   = in_sizes[2];
    int B         = in_sizes[5];
    int n_total_f = n_user_f + n_item_f;
    int n_users   = n_user_f / D;
    int n_nodes   = n_total_f / D;
    int n4        = n_total_f >> 2;
    int nblk      = (n_nodes + SCAN_B - 1) / SCAN_B;
    int gnode     = (n_nodes + 255) / 256;

    init_kernel<<<(n4 + 255) / 256, 256>>>(ue, ie, n_user_f, n4, n_nodes);
    hist_kernel<<<(n_edges + 255) / 256, 256>>>(edst, n_edges);
    scanA_kernel<<<nblk, SCAN_B>>>(n_nodes);
    scanB_kernel<<<1, SCAN_B>>>(nblk, n_nodes);
    scanC_kernel<<<nblk, SCAN_B>>>(n_nodes);
    nodeprep_kernel<<<gnode, 256>>>(n_nodes);
    dscan_kernel<<<1, NBINS>>>();
    dscatter_kernel<<<gnode, 256>>>(n_nodes);
    scatter_kernel<<<(n_edges + 255) / 256, 256>>>(esrc, edst, ew, n_edges);

    long long td = (long long)n_nodes * 16;
    int gd = (int)((td + 255) / 256);
    // Layer 1: x1 = A x0   (g_x -> g_y)
    spmm_dense_kernel<<<gd, 256>>>(n_nodes, 0);
    // Layer 2: x2 = A x1   (g_y -> g_x)
    spmm_dense_kernel<<<gd, 256>>>(n_nodes, 1);
    // Layer 3: x3 = A x2 only at sampled rows (g_x -> g_b3)
    int gl = (2 * B * 16 + 255) / 256;
    spmm_list_kernel<<<gl, 256>>>(users, items, B, n_users);

    score_kernel<<<(B * 32 + 255) / 256, 256>>>(ue, ie, users, items,
                                                (float*)d_out, B, n_users);
}

// round 12
// speedup vs baseline: 1.4228x; 1.4228x over previous
#include <cuda_runtime.h>
#include <cuda_fp16.h>

#define D 64
#define MAX_NODES 150016
#define MAX_EDGES 2100000
#define SCAN_B 512
#define MAX_BLKS ((MAX_NODES + SCAN_B - 1) / SCAN_B)

// Static scratch (allocation-free rule). Kernels bind these symbols directly;
// never passed from host as kernel args (host-side decay bug, R4).
__device__ float  g_x[(size_t)MAX_NODES * D];   // x0 concat (fp32)
__device__ __half g_h1[(size_t)MAX_NODES * D];  // x1 (fp16 storage)
__device__ __half g_h2[(size_t)MAX_NODES * D];  // x2 (fp16 storage)
__device__ float  g_b3[(size_t)MAX_NODES * D];  // x3 (fp32, sampled rows only)
__device__ int    g_cnt[MAX_NODES];             // per-dst edge counts
__device__ int    g_off[MAX_NODES + 1];         // CSR offsets
__device__ int    g_cur[MAX_NODES];             // scatter cursors
__device__ int    g_bsum[MAX_BLKS];             // per-block sums for scan
__device__ int2   g_edge[MAX_EDGES];            // dst-grouped packed (src, w-bits)

// fp16x4 <-> float4 helpers (8-byte vector load/store).
__device__ __forceinline__ float4 h4_load(const __half* p) {
    uint2 u = *(const uint2*)p;
    float2 f0 = __half22float2(*(const __half2*)&u.x);
    float2 f1 = __half22float2(*(const __half2*)&u.y);
    return make_float4(f0.x, f0.y, f1.x, f1.y);
}
__device__ __forceinline__ void h4_store(__half* p, float4 v) {
    __half2 h0 = __floats2half2_rn(v.x, v.y);
    __half2 h1 = __floats2half2_rn(v.z, v.w);
    uint2 u;
    u.x = *(const unsigned int*)&h0;
    u.y = *(const unsigned int*)&h1;
    *(uint2*)p = u;
}

// Concatenate user/item embeddings into g_x (x0); zero the histogram counts.
__global__ void init_kernel(const float* __restrict__ ue,
                            const float* __restrict__ ie,
                            int n_user_f, int n4, int n_nodes) {
    int i = blockIdx.x * blockDim.x + threadIdx.x;   // float4 index
    if (i < n_nodes) g_cnt[i] = 0;
    if (i >= n4) return;
    int f = i << 2;
    float4 v = (f < n_user_f) ? ((const float4*)ue)[i]
                              : ((const float4*)ie)[i - (n_user_f >> 2)];
    ((float4*)g_x)[i] = v;
}

__global__ void hist_kernel(const int* __restrict__ dst, int n_edges) {
    int e = blockIdx.x * blockDim.x + threadIdx.x;
    if (e < n_edges) atomicAdd(&g_cnt[dst[e]], 1);
}

// Block-wide inclusive scan of one int per thread (SCAN_B threads).
__device__ __forceinline__ int block_incl_scan(int v) {
    __shared__ int wsum[SCAN_B / 32];
    int lane = threadIdx.x & 31;
    int wid  = threadIdx.x >> 5;
    int x = v;
    #pragma unroll
    for (int o = 1; o < 32; o <<= 1) {
        int t = __shfl_up_sync(0xffffffffu, x, o);
        if (lane >= o) x += t;
    }
    if (lane == 31) wsum[wid] = x;
    __syncthreads();
    if (wid == 0) {
        int w = (lane < SCAN_B / 32) ? wsum[lane] : 0;
        #pragma unroll
        for (int o = 1; o < SCAN_B / 32; o <<= 1) {
            int t = __shfl_up_sync(0xffffffffu, w, o);
            if (lane >= o) w += t;
        }
        if (lane < SCAN_B / 32) wsum[lane] = w;
    }
    __syncthreads();
    return x + (wid ? wsum[wid - 1] : 0);
}

__global__ void scanA_kernel(int n) {
    int i = blockIdx.x * SCAN_B + threadIdx.x;
    int v = (i < n) ? g_cnt[i] : 0;
    int inc = block_incl_scan(v);
    if (i < n) g_off[i] = inc - v;
    if (threadIdx.x == SCAN_B - 1) g_bsum[blockIdx.x] = inc;
}

__global__ void scanB_kernel(int nblk, int n) {
    int v = (threadIdx.x < nblk) ? g_bsum[threadIdx.x] : 0;
    int inc = block_incl_scan(v);
    if (threadIdx.x < nblk) g_bsum[threadIdx.x] = inc - v;
    if (threadIdx.x == SCAN_B - 1) g_off[n] = inc;
}

__global__ void scanC_kernel(int n) {
    int i = blockIdx.x * SCAN_B + threadIdx.x;
    if (i < n) {
        int o = g_off[i] + g_bsum[blockIdx.x];
        g_off[i] = o;
        g_cur[i] = o;
    }
}

__global__ void scatter_kernel(const int* __restrict__ src,
                               const int* __restrict__ dst,
                               const float* __restrict__ w, int n_edges) {
    int e = blockIdx.x * blockDim.x + threadIdx.x;
    if (e >= n_edges) return;
    int d = dst[e];
    int pos = atomicAdd(&g_cur[d], 1);
    g_edge[pos] = make_int2(src[e], __float_as_int(w[e]));
}

// Row-gather (fp32 source), 4-deep unroll + remainder (R8 structure).
__device__ __forceinline__ float4 row_gather_f(const float* __restrict__ x,
                                               int node, int c) {
    int beg = g_off[node];
    int end = g_off[node + 1];
    float4 a = make_float4(0.f, 0.f, 0.f, 0.f);
    int i = beg;
    for (; i + 4 <= end; i += 4) {
        int2 p0 = g_edge[i];
        int2 p1 = g_edge[i + 1];
        int2 p2 = g_edge[i + 2];
        int2 p3 = g_edge[i + 3];
        float4 v0 = *(const float4*)(x + (size_t)p0.x * D + c);
        float4 v1 = *(const float4*)(x + (size_t)p1.x * D + c);
        float4 v2 = *(const float4*)(x + (size_t)p2.x * D + c);
        float4 v3 = *(const float4*)(x + (size_t)p3.x * D + c);
        float w0 = __int_as_float(p0.y);
        float w1 = __int_as_float(p1.y);
        float w2 = __int_as_float(p2.y);
        float w3 = __int_as_float(p3.y);
        a.x += w0 * v0.x + w1 * v1.x + w2 * v2.x + w3 * v3.x;
        a.y += w0 * v0.y + w1 * v1.y + w2 * v2.y + w3 * v3.y;
        a.z += w0 * v0.z + w1 * v1.z + w2 * v2.z + w3 * v3.z;
        a.w += w0 * v0.w + w1 * v1.w + w2 * v2.w + w3 * v3.w;
    }
    for (; i < end; i++) {
        int2 p = g_edge[i];
        float4 v = *(const float4*)(x + (size_t)p.x * D + c);
        float ww = __int_as_float(p.y);
        a.x += ww * v.x; a.y += ww * v.y; a.z += ww * v.z; a.w += ww * v.w;
    }
    return a;
}

// Row-gather (fp16 source), same structure; 8B loads per src row slice.
__device__ __forceinline__ float4 row_gather_h(const __half* __restrict__ x,
                                               int node, int c) {
    int beg = g_off[node];
    int end = g_off[node + 1];
    float4 a = make_float4(0.f, 0.f, 0.f, 0.f);
    int i = beg;
    for (; i + 4 <= end; i += 4) {
        int2 p0 = g_edge[i];
        int2 p1 = g_edge[i + 1];
        int2 p2 = g_edge[i + 2];
        int2 p3 = g_edge[i + 3];
        float4 v0 = h4_load(x + (size_t)p0.x * D + c);
        float4 v1 = h4_load(x + (size_t)p1.x * D + c);
        float4 v2 = h4_load(x + (size_t)p2.x * D + c);
        float4 v3 = h4_load(x + (size_t)p3.x * D + c);
        float w0 = __int_as_float(p0.y);
        float w1 = __int_as_float(p1.y);
        float w2 = __int_as_float(p2.y);
        float w3 = __int_as_float(p3.y);
        a.x += w0 * v0.x + w1 * v1.x + w2 * v2.x + w3 * v3.x;
        a.y += w0 * v0.y + w1 * v1.y + w2 * v2.y + w3 * v3.y;
        a.z += w0 * v0.z + w1 * v1.z + w2 * v2.z + w3 * v3.z;
        a.w += w0 * v0.w + w1 * v1.w + w2 * v2.w + w3 * v3.w;
    }
    for (; i < end; i++) {
        int2 p = g_edge[i];
        float4 v = h4_load(x + (size_t)p.x * D + c);
        float ww = __int_as_float(p.y);
        a.x += ww * v.x; a.y += ww * v.y; a.z += ww * v.z; a.w += ww * v.w;
    }
    return a;
}

// Layer 1: x1 = A x0, fp32 source -> fp16 dest.
__global__ void spmm_f2h_kernel(int n_nodes) {
    int t = blockIdx.x * blockDim.x + threadIdx.x;
    int node = t >> 4;
    if (node >= n_nodes) return;
    int c = (t & 15) << 2;
    float4 a = row_gather_f(g_x, node, c);
    h4_store(g_h1 + (size_t)node * D + c, a);
}

// Layer 2: x2 = A x1, fp16 source -> fp16 dest.
__global__ void spmm_h2h_kernel(int n_nodes) {
    int t = blockIdx.x * blockDim.x + threadIdx.x;
    int node = t >> 4;
    if (node >= n_nodes) return;
    int c = (t & 15) << 2;
    float4 a = row_gather_h(g_h1, node, c);
    h4_store(g_h2 + (size_t)node * D + c, a);
}

// Layer 3 (sampled rows only): x3 = A x2, fp16 source -> fp32 dest.
__global__ void spmm_list_kernel(const int* __restrict__ users,
                                 const int* __restrict__ items,
                                 int B, int n_users) {
    int t = blockIdx.x * blockDim.x + threadIdx.x;
    int li = t >> 4;
    if (li >= 2 * B) return;
    int node = (li < B) ? users[li] : n_users + items[li - B];
    int c = (t & 15) << 2;
    float4 a = row_gather_h(g_h2, node, c);
    *(float4*)(g_b3 + (size_t)node * D + c) = a;
}

// One warp per (user, item) pair. Final row = (x0+x1+x2+x3)/4 on the fly
// from ue/ie (fp32), g_h1/g_h2 (fp16), g_b3 (fp32). 1/16 folded into dot.
__global__ void score_kernel(const float* __restrict__ ue,
                             const float* __restrict__ ie,
                             const int* __restrict__ users,
                             const int* __restrict__ items,
                             float* __restrict__ out, int B, int n_users) {
    int g    = blockIdx.x * blockDim.x + threadIdx.x;
    int pair = g >> 5;
    int lane = threadIdx.x & 31;
    if (pair >= B) return;
    int un = users[pair];
    int in = items[pair];
    int ir = n_users + in;
    size_t uo = (size_t)un * D + lane * 2;
    size_t io = (size_t)ir * D + lane * 2;
    float2 u0 = *(const float2*)(ue + (size_t)un * D + lane * 2);
    float2 u1 = __half22float2(*(const __half2*)(g_h1 + uo));
    float2 u2 = __half22float2(*(const __half2*)(g_h2 + uo));
    float2 u3 = *(const float2*)(g_b3 + uo);
    float2 v0 = *(const float2*)(ie + (size_t)in * D + lane * 2);
    float2 v1 = __half22float2(*(const __half2*)(g_h1 + io));
    float2 v2 = __half22float2(*(const __half2*)(g_h2 + io));
    float2 v3 = *(const float2*)(g_b3 + io);
    float ux = u0.x + u1.x + u2.x + u3.x;
    float uy = u0.y + u1.y + u2.y + u3.y;
    float vx = v0.x + v1.x + v2.x + v3.x;
    float vy = v0.y + v1.y + v2.y + v3.y;
    float s = ux * vx + uy * vy;
    #pragma unroll
    for (int o = 16; o; o >>= 1) s += __shfl_xor_sync(0xffffffffu, s, o);
    if (lane == 0) out[pair] = s * (1.0f / 16.0f);
}

extern "C" void kernel_launch(void* const* d_in, const int* in_sizes, int n_in,
                              void* d_out, int out_size) {
    const float* ue    = (const float*)d_in[0];
    const float* ie    = (const float*)d_in[1];
    const int*   esrc  = (const int*)  d_in[2];
    const int*   edst  = (const int*)  d_in[3];
    const float* ew    = (const float*)d_in[4];
    const int*   users = (const int*)  d_in[5];
    const int*   items = (const int*)  d_in[6];

    int n_user_f  = in_sizes[0];
    int n_item_f  = in_sizes[1];
    int n_edges   = in_sizes[2];
    int B         = in_sizes[5];
    int n_total_f = n_user_f + n_item_f;
    int n_users   = n_user_f / D;
    int n_nodes   = n_total_f / D;
    int n4        = n_total_f >> 2;
    int nblk      = (n_nodes + SCAN_B - 1) / SCAN_B;

    init_kernel<<<(n4 + 255) / 256, 256>>>(ue, ie, n_user_f, n4, n_nodes);
    hist_kernel<<<(n_edges + 255) / 256, 256>>>(edst, n_edges);
    scanA_kernel<<<nblk, SCAN_B>>>(n_nodes);
    scanB_kernel<<<1, SCAN_B>>>(nblk, n_nodes);
    scanC_kernel<<<nblk, SCAN_B>>>(n_nodes);
    scatter_kernel<<<(n_edges + 255) / 256, 256>>>(esrc, edst, ew, n_edges);

    long long td = (long long)n_nodes * 16;
    int gd = (int)((td + 255) / 256);
    spmm_f2h_kernel<<<gd, 256>>>(n_nodes);              // x1 = A x0
    spmm_h2h_kernel<<<gd, 256>>>(n_nodes);              // x2 = A x1
    int gl = (2 * B * 16 + 255) / 256;
    spmm_list_kernel<<<gl, 256>>>(users, items, B, n_users);  // x3 @ samples

    score_kernel<<<(B * 32 + 255) / 256, 256>>>(ue, ie, users, items,
                                                (float*)d_out, B, n_users);
}

// round 13
// speedup vs baseline: 1.5325x; 1.0771x over previous
#include <cuda_runtime.h>
#include <cuda_fp16.h>

#define D 64
#define MAX_NODES 150016
#define MAX_EDGES 2100000
#define SCAN_B 512
#define MAX_BLKS ((MAX_NODES + SCAN_B - 1) / SCAN_B)

// Static scratch (allocation-free rule). Kernels bind these symbols directly;
// never passed from host as kernel args (host-side decay bug, R4).
__device__ __half g_h0[(size_t)MAX_NODES * D];  // x0 concat (fp16 gather copy)
__device__ __half g_h1[(size_t)MAX_NODES * D];  // x1 (fp16 storage)
__device__ __half g_h2[(size_t)MAX_NODES * D];  // x2 (fp16 storage)
__device__ float  g_b3[(size_t)MAX_NODES * D];  // x3 (fp32, sampled rows only)
__device__ int    g_cnt[MAX_NODES];             // per-dst edge counts
__device__ int    g_off[MAX_NODES + 1];         // CSR offsets
__device__ int    g_cur[MAX_NODES];             // scatter cursors
__device__ int    g_bsum[MAX_BLKS];             // per-block sums for scan
__device__ int2   g_edge[MAX_EDGES];            // dst-grouped packed (src, w-bits)

// fp16x4 <-> float4 helpers (8-byte vector load/store).
__device__ __forceinline__ float4 h4_load(const __half* p) {
    uint2 u = *(const uint2*)p;
    float2 f0 = __half22float2(*(const __half2*)&u.x);
    float2 f1 = __half22float2(*(const __half2*)&u.y);
    return make_float4(f0.x, f0.y, f1.x, f1.y);
}
__device__ __forceinline__ void h4_store(__half* p, float4 v) {
    __half2 h0 = __floats2half2_rn(v.x, v.y);
    __half2 h1 = __floats2half2_rn(v.z, v.w);
    uint2 u;
    u.x = *(const unsigned int*)&h0;
    u.y = *(const unsigned int*)&h1;
    *(uint2*)p = u;
}

// Concatenate user/item embeddings into g_h0 (fp16 x0); zero hist counts.
__global__ void init_kernel(const float* __restrict__ ue,
                            const float* __restrict__ ie,
                            int n_user_f, int n4, int n_nodes) {
    int i = blockIdx.x * blockDim.x + threadIdx.x;   // float4 index
    if (i < n_nodes) g_cnt[i] = 0;
    if (i >= n4) return;
    int f = i << 2;
    float4 v = (f < n_user_f) ? ((const float4*)ue)[i]
                              : ((const float4*)ie)[i - (n_user_f >> 2)];
    h4_store(g_h0 + ((size_t)i << 2), v);
}

__global__ void hist_kernel(const int* __restrict__ dst, int n_edges) {
    int e = blockIdx.x * blockDim.x + threadIdx.x;
    if (e < n_edges) atomicAdd(&g_cnt[dst[e]], 1);
}

// Block-wide inclusive scan of one int per thread (SCAN_B threads).
__device__ __forceinline__ int block_incl_scan(int v) {
    __shared__ int wsum[SCAN_B / 32];
    int lane = threadIdx.x & 31;
    int wid  = threadIdx.x >> 5;
    int x = v;
    #pragma unroll
    for (int o = 1; o < 32; o <<= 1) {
        int t = __shfl_up_sync(0xffffffffu, x, o);
        if (lane >= o) x += t;
    }
    if (lane == 31) wsum[wid] = x;
    __syncthreads();
    if (wid == 0) {
        int w = (lane < SCAN_B / 32) ? wsum[lane] : 0;
        #pragma unroll
        for (int o = 1; o < SCAN_B / 32; o <<= 1) {
            int t = __shfl_up_sync(0xffffffffu, w, o);
            if (lane >= o) w += t;
        }
        if (lane < SCAN_B / 32) wsum[lane] = w;
    }
    __syncthreads();
    return x + (wid ? wsum[wid - 1] : 0);
}

__global__ void scanA_kernel(int n) {
    int i = blockIdx.x * SCAN_B + threadIdx.x;
    int v = (i < n) ? g_cnt[i] : 0;
    int inc = block_incl_scan(v);
    if (i < n) g_off[i] = inc - v;
    if (threadIdx.x == SCAN_B - 1) g_bsum[blockIdx.x] = inc;
}

__global__ void scanB_kernel(int nblk, int n) {
    int v = (threadIdx.x < nblk) ? g_bsum[threadIdx.x] : 0;
    int inc = block_incl_scan(v);
    if (threadIdx.x < nblk) g_bsum[threadIdx.x] = inc - v;
    if (threadIdx.x == SCAN_B - 1) g_off[n] = inc;
}

__global__ void scanC_kernel(int n) {
    int i = blockIdx.x * SCAN_B + threadIdx.x;
    if (i < n) {
        int o = g_off[i] + g_bsum[blockIdx.x];
        g_off[i] = o;
        g_cur[i] = o;
    }
}

__global__ void scatter_kernel(const int* __restrict__ src,
                               const int* __restrict__ dst,
                               const float* __restrict__ w, int n_edges) {
    int e = blockIdx.x * blockDim.x + threadIdx.x;
    if (e >= n_edges) return;
    int d = dst[e];
    int pos = atomicAdd(&g_cur[d], 1);
    g_edge[pos] = make_int2(src[e], __float_as_int(w[e]));
}

// Row-gather (fp16 source), 4-deep unroll + remainder; 8B loads per slice.
__device__ __forceinline__ float4 row_gather_h(const __half* __restrict__ x,
                                               int node, int c) {
    int beg = g_off[node];
    int end = g_off[node + 1];
    float4 a = make_float4(0.f, 0.f, 0.f, 0.f);
    int i = beg;
    for (; i + 4 <= end; i += 4) {
        int2 p0 = g_edge[i];
        int2 p1 = g_edge[i + 1];
        int2 p2 = g_edge[i + 2];
        int2 p3 = g_edge[i + 3];
        float4 v0 = h4_load(x + (size_t)p0.x * D + c);
        float4 v1 = h4_load(x + (size_t)p1.x * D + c);
        float4 v2 = h4_load(x + (size_t)p2.x * D + c);
        float4 v3 = h4_load(x + (size_t)p3.x * D + c);
        float w0 = __int_as_float(p0.y);
        float w1 = __int_as_float(p1.y);
        float w2 = __int_as_float(p2.y);
        float w3 = __int_as_float(p3.y);
        a.x += w0 * v0.x + w1 * v1.x + w2 * v2.x + w3 * v3.x;
        a.y += w0 * v0.y + w1 * v1.y + w2 * v2.y + w3 * v3.y;
        a.z += w0 * v0.z + w1 * v1.z + w2 * v2.z + w3 * v3.z;
        a.w += w0 * v0.w + w1 * v1.w + w2 * v2.w + w3 * v3.w;
    }
    for (; i < end; i++) {
        int2 p = g_edge[i];
        float4 v = h4_load(x + (size_t)p.x * D + c);
        float ww = __int_as_float(p.y);
        a.x += ww * v.x; a.y += ww * v.y; a.z += ww * v.z; a.w += ww * v.w;
    }
    return a;
}

// Dense SpMM, fp16 -> fp16. which=0: g_h0 -> g_h1; which=1: g_h1 -> g_h2.
__global__ void spmm_h2h_kernel(int n_nodes, int which) {
    const __half* __restrict__ x = which ? g_h1 : g_h0;
    __half*                    y = which ? g_h2 : g_h1;
    int t = blockIdx.x * blockDim.x + threadIdx.x;
    int node = t >> 4;
    if (node >= n_nodes) return;
    int c = (t & 15) << 2;
    float4 a = row_gather_h(x, node, c);
    h4_store(y + (size_t)node * D + c, a);
}

// Layer 3 (sampled rows only): x3 = A x2, fp16 source -> fp32 dest.
__global__ void spmm_list_kernel(const int* __restrict__ users,
                                 const int* __restrict__ items,
                                 int B, int n_users) {
    int t = blockIdx.x * blockDim.x + threadIdx.x;
    int li = t >> 4;
    if (li >= 2 * B) return;
    int node = (li < B) ? users[li] : n_users + items[li - B];
    int c = (t & 15) << 2;
    float4 a = row_gather_h(g_h2, node, c);
    *(float4*)(g_b3 + (size_t)node * D + c) = a;
}

// One warp per (user, item) pair. Final row = (x0+x1+x2+x3)/4 on the fly
// from ue/ie (exact fp32 x0), g_h1/g_h2 (fp16), g_b3 (fp32). 1/16 folded in.
__global__ void score_kernel(const float* __restrict__ ue,
                             const float* __restrict__ ie,
                             const int* __restrict__ users,
                             const int* __restrict__ items,
                             float* __restrict__ out, int B, int n_users) {
    int g    = blockIdx.x * blockDim.x + threadIdx.x;
    int pair = g >> 5;
    int lane = threadIdx.x & 31;
    if (pair >= B) return;
    int un = users[pair];
    int in = items[pair];
    int ir = n_users + in;
    size_t uo = (size_t)un * D + lane * 2;
    size_t io = (size_t)ir * D + lane * 2;
    float2 u0 = *(const float2*)(ue + (size_t)un * D + lane * 2);
    float2 u1 = __half22float2(*(const __half2*)(g_h1 + uo));
    float2 u2 = __half22float2(*(const __half2*)(g_h2 + uo));
    float2 u3 = *(const float2*)(g_b3 + uo);
    float2 v0 = *(const float2*)(ie + (size_t)in * D + lane * 2);
    float2 v1 = __half22float2(*(const __half2*)(g_h1 + io));
    float2 v2 = __half22float2(*(const __half2*)(g_h2 + io));
    float2 v3 = *(const float2*)(g_b3 + io);
    float ux = u0.x + u1.x + u2.x + u3.x;
    float uy = u0.y + u1.y + u2.y + u3.y;
    float vx = v0.x + v1.x + v2.x + v3.x;
    float vy = v0.y + v1.y + v2.y + v3.y;
    float s = ux * vx + uy * vy;
    #pragma unroll
    for (int o = 16; o; o >>= 1) s += __shfl_xor_sync(0xffffffffu, s, o);
    if (lane == 0) out[pair] = s * (1.0f / 16.0f);
}

extern "C" void kernel_launch(void* const* d_in, const int* in_sizes, int n_in,
                              void* d_out, int out_size) {
    const float* ue    = (const float*)d_in[0];
    const float* ie    = (const float*)d_in[1];
    const int*   esrc  = (const int*)  d_in[2];
    const int*   edst  = (const int*)  d_in[3];
    const float* ew    = (const float*)d_in[4];
    const int*   users = (const int*)  d_in[5];
    const int*   items = (const int*)  d_in[6];

    int n_user_f  = in_sizes[0];
    int n_item_f  = in_sizes[1];
    int n_edges   = in_sizes[2];
    int B         = in_sizes[5];
    int n_total_f = n_user_f + n_item_f;
    int n_users   = n_user_f / D;
    int n_nodes   = n_total_f / D;
    int n4        = n_total_f >> 2;
    int nblk      = (n_nodes + SCAN_B - 1) / SCAN_B;

    init_kernel<<<(n4 + 255) / 256, 256>>>(ue, ie, n_user_f, n4, n_nodes);
    hist_kernel<<<(n_edges + 255) / 256, 256>>>(edst, n_edges);
    scanA_kernel<<<nblk, SCAN_B>>>(n_nodes);
    scanB_kernel<<<1, SCAN_B>>>(nblk, n_nodes);
    scanC_kernel<<<nblk, SCAN_B>>>(n_nodes);
    scatter_kernel<<<(n_edges + 255) / 256, 256>>>(esrc, edst, ew, n_edges);

    long long td = (long long)n_nodes * 16;
    int gd = (int)((td + 255) / 256);
    spmm_h2h_kernel<<<gd, 256>>>(n_nodes, 0);           // x1 = A x0 (fp16 in)
    spmm_h2h_kernel<<<gd, 256>>>(n_nodes, 1);           // x2 = A x1
    int gl = (2 * B * 16 + 255) / 256;
    spmm_list_kernel<<<gl, 256>>>(users, items, B, n_users);  // x3 @ samples

    score_kernel<<<(B * 32 + 255) / 256, 256>>>(ue, ie, users, items,
                                                (float*)d_out, B, n_users);
}

// round 14
// speedup vs baseline: 1.6164x; 1.0548x over previous
#include <cuda_runtime.h>
#include <cuda_fp16.h>

#define D 64
#define MAX_NODES 150016
#define MAX_EDGES 2100000
#define SCAN_B 512
#define MAX_BLKS ((MAX_NODES + SCAN_B - 1) / SCAN_B)

// Static scratch (allocation-free rule). Kernels bind these symbols directly.
__device__ __half g_h0[(size_t)MAX_NODES * D];  // x0 concat (fp16)
__device__ __half g_h1[(size_t)MAX_NODES * D];  // x1 (fp16)
__device__ __half g_h2[(size_t)MAX_NODES * D];  // x2 (fp16)
__device__ float  g_b3[(size_t)MAX_NODES * D];  // x3 (fp32, sampled rows only)
__device__ int    g_cnt[MAX_NODES];             // per-dst edge counts
__device__ int    g_off[MAX_NODES + 1];         // CSR offsets
__device__ int    g_cur[MAX_NODES];             // scatter cursors
__device__ int    g_bsum[MAX_BLKS];             // per-block sums for scan
__device__ int2   g_edge[MAX_EDGES];            // dst-grouped packed (src, w-bits)

__device__ __forceinline__ void h4_store(__half* p, float4 v) {
    __half2 h0 = __floats2half2_rn(v.x, v.y);
    __half2 h1 = __floats2half2_rn(v.z, v.w);
    uint2 u;
    u.x = *(const unsigned int*)&h0;
    u.y = *(const unsigned int*)&h1;
    *(uint2*)p = u;
}
// 8 halves (16B) -> two float4
__device__ __forceinline__ void h8_expand(uint4 u, float4& a, float4& b) {
    float2 f0 = __half22float2(*(const __half2*)&u.x);
    float2 f1 = __half22float2(*(const __half2*)&u.y);
    float2 f2 = __half22float2(*(const __half2*)&u.z);
    float2 f3 = __half22float2(*(const __half2*)&u.w);
    a = make_float4(f0.x, f0.y, f1.x, f1.y);
    b = make_float4(f2.x, f2.y, f3.x, f3.y);
}
__device__ __forceinline__ void h8_store(__half* p, float4 a, float4 b) {
    __half2 h0 = __floats2half2_rn(a.x, a.y);
    __half2 h1 = __floats2half2_rn(a.z, a.w);
    __half2 h2 = __floats2half2_rn(b.x, b.y);
    __half2 h3 = __floats2half2_rn(b.z, b.w);
    uint4 u;
    u.x = *(const unsigned int*)&h0;
    u.y = *(const unsigned int*)&h1;
    u.z = *(const unsigned int*)&h2;
    u.w = *(const unsigned int*)&h3;
    *(uint4*)p = u;
}
__device__ __forceinline__ void fma8(uint4 u, float w, float4& a, float4& b) {
    float4 x, y;
    h8_expand(u, x, y);
    a.x += w * x.x; a.y += w * x.y; a.z += w * x.z; a.w += w * x.w;
    b.x += w * y.x; b.y += w * y.y; b.z += w * y.z; b.w += w * y.w;
}

// Concatenate user/item embeddings into g_h0 (fp16 x0); zero hist counts.
__global__ void init_kernel(const float* __restrict__ ue,
                            const float* __restrict__ ie,
                            int n_user_f, int n4, int n_nodes) {
    int i = blockIdx.x * blockDim.x + threadIdx.x;   // float4 index
    if (i < n_nodes) g_cnt[i] = 0;
    if (i >= n4) return;
    int f = i << 2;
    float4 v = (f < n_user_f) ? ((const float4*)ue)[i]
                              : ((const float4*)ie)[i - (n_user_f >> 2)];
    h4_store(g_h0 + ((size_t)i << 2), v);
}

// Histogram, 4 edges per thread (int4 loads).
__global__ void hist_kernel(const int* __restrict__ dst, int n_edges) {
    int i = blockIdx.x * blockDim.x + threadIdx.x;
    int base = i << 2;
    if (base >= n_edges) return;
    if (base + 4 <= n_edges) {
        int4 d = *(const int4*)(dst + base);
        atomicAdd(&g_cnt[d.x], 1);
        atomicAdd(&g_cnt[d.y], 1);
        atomicAdd(&g_cnt[d.z], 1);
        atomicAdd(&g_cnt[d.w], 1);
    } else {
        for (int e = base; e < n_edges; e++) atomicAdd(&g_cnt[dst[e]], 1);
    }
}

// Block-wide inclusive scan of one int per thread (SCAN_B threads).
__device__ __forceinline__ int block_incl_scan(int v) {
    __shared__ int wsum[SCAN_B / 32];
    int lane = threadIdx.x & 31;
    int wid  = threadIdx.x >> 5;
    int x = v;
    #pragma unroll
    for (int o = 1; o < 32; o <<= 1) {
        int t = __shfl_up_sync(0xffffffffu, x, o);
        if (lane >= o) x += t;
    }
    if (lane == 31) wsum[wid] = x;
    __syncthreads();
    if (wid == 0) {
        int w = (lane < SCAN_B / 32) ? wsum[lane] : 0;
        #pragma unroll
        for (int o = 1; o < SCAN_B / 32; o <<= 1) {
            int t = __shfl_up_sync(0xffffffffu, w, o);
            if (lane >= o) w += t;
        }
        if (lane < SCAN_B / 32) wsum[lane] = w;
    }
    __syncthreads();
    return x + (wid ? wsum[wid - 1] : 0);
}

// Pass A: local exclusive prefix -> g_off, block total -> g_bsum.
__global__ void scanA_kernel(int n) {
    int i = blockIdx.x * SCAN_B + threadIdx.x;
    int v = (i < n) ? g_cnt[i] : 0;
    int inc = block_incl_scan(v);
    if (i < n) g_off[i] = inc - v;
    if (threadIdx.x == SCAN_B - 1) g_bsum[blockIdx.x] = inc;
}

// Pass C (merged with old B): each block reduces g_bsum[0..b) itself,
// adds to its elements, mirrors cursors; last block writes g_off[n].
__global__ void scanC_kernel(int n, int nblk) {
    __shared__ int wsum[SCAN_B / 32];
    int b = blockIdx.x;
    int lane = threadIdx.x & 31;
    int wid  = threadIdx.x >> 5;
    int acc = 0;
    for (int j = threadIdx.x; j < b; j += SCAN_B) acc += g_bsum[j];
    #pragma unroll
    for (int o = 16; o; o >>= 1) acc += __shfl_xor_sync(0xffffffffu, acc, o);
    if (lane == 0) wsum[wid] = acc;
    __syncthreads();
    if (wid == 0) {
        int v = (lane < SCAN_B / 32) ? wsum[lane] : 0;
        #pragma unroll
        for (int o = (SCAN_B / 64); o; o >>= 1)
            v += __shfl_xor_sync(0xffffffffu, v, o);
        if (lane == 0) wsum[0] = v;
    }
    __syncthreads();
    int total = wsum[0];
    int i = b * SCAN_B + threadIdx.x;
    if (i < n) {
        int o = g_off[i] + total;
        g_off[i] = o;
        g_cur[i] = o;
    }
    if (b == nblk - 1 && threadIdx.x == 0) g_off[n] = total + g_bsum[b];
}

// Scatter, 4 edges per thread (int4/float4 loads).
__global__ void scatter_kernel(const int* __restrict__ src,
                               const int* __restrict__ dst,
                               const float* __restrict__ w, int n_edges) {
    int i = blockIdx.x * blockDim.x + threadIdx.x;
    int base = i << 2;
    if (base >= n_edges) return;
    if (base + 4 <= n_edges) {
        int4   s = *(const int4*)  (src + base);
        int4   d = *(const int4*)  (dst + base);
        float4 v = *(const float4*)(w   + base);
        int p;
        p = atomicAdd(&g_cur[d.x], 1); g_edge[p] = make_int2(s.x, __float_as_int(v.x));
        p = atomicAdd(&g_cur[d.y], 1); g_edge[p] = make_int2(s.y, __float_as_int(v.y));
        p = atomicAdd(&g_cur[d.z], 1); g_edge[p] = make_int2(s.z, __float_as_int(v.z));
        p = atomicAdd(&g_cur[d.w], 1); g_edge[p] = make_int2(s.w, __float_as_int(v.w));
    } else {
        for (int e = base; e < n_edges; e++) {
            int p = atomicAdd(&g_cur[dst[e]], 1);
            g_edge[p] = make_int2(src[e], __float_as_int(w[e]));
        }
    }
}

// Row-gather (fp16 source), 8 thr/node, 16B loads, 4-deep unroll + remainder.
__device__ __forceinline__ void row_gather8(const __half* __restrict__ x,
                                            int node, int c,
                                            float4& a0, float4& a1) {
    int beg = g_off[node];
    int end = g_off[node + 1];
    a0 = make_float4(0.f, 0.f, 0.f, 0.f);
    a1 = make_float4(0.f, 0.f, 0.f, 0.f);
    int i = beg;
    for (; i + 4 <= end; i += 4) {
        int2 p0 = g_edge[i];
        int2 p1 = g_edge[i + 1];
        int2 p2 = g_edge[i + 2];
        int2 p3 = g_edge[i + 3];
        uint4 u0 = *(const uint4*)(x + (size_t)p0.x * D + c);
        uint4 u1 = *(const uint4*)(x + (size_t)p1.x * D + c);
        uint4 u2 = *(const uint4*)(x + (size_t)p2.x * D + c);
        uint4 u3 = *(const uint4*)(x + (size_t)p3.x * D + c);
        fma8(u0, __int_as_float(p0.y), a0, a1);
        fma8(u1, __int_as_float(p1.y), a0, a1);
        fma8(u2, __int_as_float(p2.y), a0, a1);
        fma8(u3, __int_as_float(p3.y), a0, a1);
    }
    for (; i < end; i++) {
        int2 p = g_edge[i];
        uint4 u = *(const uint4*)(x + (size_t)p.x * D + c);
        fma8(u, __int_as_float(p.y), a0, a1);
    }
}

// Dense SpMM, fp16 -> fp16, 8 threads/node. which=0: h0->h1; 1: h1->h2.
__global__ void spmm_h2h_kernel(int n_nodes, int which) {
    const __half* __restrict__ x = which ? g_h1 : g_h0;
    __half*                    y = which ? g_h2 : g_h1;
    int t = blockIdx.x * blockDim.x + threadIdx.x;
    int node = t >> 3;
    if (node >= n_nodes) return;
    int c = (t & 7) << 3;                  // half offset: 0..56
    float4 a0, a1;
    row_gather8(x, node, c, a0, a1);
    h8_store(y + (size_t)node * D + c, a0, a1);
}

// Layer 3 (sampled rows only): x3 = A x2, fp16 -> fp32, 8 threads/node.
__global__ void spmm_list_kernel(const int* __restrict__ users,
                                 const int* __restrict__ items,
                                 int B, int n_users) {
    int t = blockIdx.x * blockDim.x + threadIdx.x;
    int li = t >> 3;
    if (li >= 2 * B) return;
    int node = (li < B) ? users[li] : n_users + items[li - B];
    int c = (t & 7) << 3;
    float4 a0, a1;
    row_gather8(g_h2, node, c, a0, a1);
    float* p = g_b3 + (size_t)node * D + c;
    *(float4*)p       = a0;
    *(float4*)(p + 4) = a1;
}

// One warp per (user, item) pair. Final row = (x0+x1+x2+x3)/4 on the fly
// from ue/ie (exact fp32 x0), g_h1/g_h2 (fp16), g_b3 (fp32). 1/16 folded in.
__global__ void score_kernel(const float* __restrict__ ue,
                             const float* __restrict__ ie,
                             const int* __restrict__ users,
                             const int* __restrict__ items,
                             float* __restrict__ out, int B, int n_users) {
    int g    = blockIdx.x * blockDim.x + threadIdx.x;
    int pair = g >> 5;
    int lane = threadIdx.x & 31;
    if (pair >= B) return;
    int un = users[pair];
    int in = items[pair];
    int ir = n_users + in;
    size_t uo = (size_t)un * D + lane * 2;
    size_t io = (size_t)ir * D + lane * 2;
    float2 u0 = *(const float2*)(ue + (size_t)un * D + lane * 2);
    float2 u1 = __half22float2(*(const __half2*)(g_h1 + uo));
    float2 u2 = __half22float2(*(const __half2*)(g_h2 + uo));
    float2 u3 = *(const float2*)(g_b3 + uo);
    float2 v0 = *(const float2*)(ie + (size_t)in * D + lane * 2);
    float2 v1 = __half22float2(*(const __half2*)(g_h1 + io));
    float2 v2 = __half22float2(*(const __half2*)(g_h2 + io));
    float2 v3 = *(const float2*)(g_b3 + io);
    float ux = u0.x + u1.x + u2.x + u3.x;
    float uy = u0.y + u1.y + u2.y + u3.y;
    float vx = v0.x + v1.x + v2.x + v3.x;
    float vy = v0.y + v1.y + v2.y + v3.y;
    float s = ux * vx + uy * vy;
    #pragma unroll
    for (int o = 16; o; o >>= 1) s += __shfl_xor_sync(0xffffffffu, s, o);
    if (lane == 0) out[pair] = s * (1.0f / 16.0f);
}

extern "C" void kernel_launch(void* const* d_in, const int* in_sizes, int n_in,
                              void* d_out, int out_size) {
    const float* ue    = (const float*)d_in[0];
    const float* ie    = (const float*)d_in[1];
    const int*   esrc  = (const int*)  d_in[2];
    const int*   edst  = (const int*)  d_in[3];
    const float* ew    = (const float*)d_in[4];
    const int*   users = (const int*)  d_in[5];
    const int*   items = (const int*)  d_in[6];

    int n_user_f  = in_sizes[0];
    int n_item_f  = in_sizes[1];
    int n_edges   = in_sizes[2];
    int B         = in_sizes[5];
    int n_total_f = n_user_f + n_item_f;
    int n_users   = n_user_f / D;
    int n_nodes   = n_total_f / D;
    int n4        = n_total_f >> 2;
    int nblk      = (n_nodes + SCAN_B - 1) / SCAN_B;
    int ne4       = (n_edges + 3) >> 2;

    init_kernel<<<(n4 + 255) / 256, 256>>>(ue, ie, n_user_f, n4, n_nodes);
    hist_kernel<<<(ne4 + 255) / 256, 256>>>(edst, n_edges);
    scanA_kernel<<<nblk, SCAN_B>>>(n_nodes);
    scanC_kernel<<<nblk, SCAN_B>>>(n_nodes, nblk);
    scatter_kernel<<<(ne4 + 255) / 256, 256>>>(esrc, edst, ew, n_edges);

    long long td = (long long)n_nodes * 8;
    int gd = (int)((td + 255) / 256);
    spmm_h2h_kernel<<<gd, 256>>>(n_nodes, 0);           // x1 = A x0
    spmm_h2h_kernel<<<gd, 256>>>(n_nodes, 1);           // x2 = A x1
    int gl = (2 * B * 8 + 255) / 256;
    spmm_list_kernel<<<gl, 256>>>(users, items, B, n_users);  // x3 @ samples

    score_kernel<<<(B * 32 + 255) / 256, 256>>>(ue, ie, users, items,
                                                (float*)d_out, B, n_users);
}